// round 9
// baseline (speedup 1.0000x reference)
#include <cuda_runtime.h>
#include <cuda_bf16.h>

#define NQ 8
#define FULLMASK 0xffffffffu

// One sample per 4 lanes; lane l owns matrix rows e0=2l and e1=2l+1.
__global__ void __launch_bounds__(256) acrobot_dyn_kernel(
    const float* __restrict__ q_in, const float* __restrict__ v_in,
    const float* __restrict__ u_in, const float* __restrict__ p,
    float* __restrict__ out, int Btot /* = B*NQ */)
{
    // ---- uniform coefficient tables (once per CTA) ----
    // sCo[i][j] = (A, IsOrD): off-diag A = ls_i*ls_j*(ms_suf_mx - .5 ms_mx), Is_suf[mx];
    //             diag       A = 0,     D[i].
    __shared__ float2 sCo[NQ][NQ + 1];
    __shared__ float sGc[NQ];   // g * ls_k * (ms_suf_k - 0.5*ms_k)
    __shared__ float sTau[NQ];

    if (threadIdx.x == 0) {
        float ms[NQ], ls[NQ], ms_suf[NQ], Is_suf[NQ];
#pragma unroll
        for (int i = 0; i < NQ; i++) {
            ms[i] = p[i];
            ls[i] = p[NQ + i];
            sTau[i] = p[2 * NQ + 1 + i];
        }
        const float g = p[2 * NQ];
        float a = 0.0f, c = 0.0f;
#pragma unroll
        for (int i = NQ - 1; i >= 0; i--) {
            a += ms[i];
            c += ms[i] * ls[i] * ls[i] * (1.0f / 12.0f);
            ms_suf[i] = a;
            Is_suf[i] = c;
        }
#pragma unroll
        for (int i = 0; i < NQ; i++) {
            sGc[i] = g * ls[i] * (ms_suf[i] - 0.5f * ms[i]);
#pragma unroll
            for (int j = 0; j < NQ; j++) {
                if (i == j) {
                    sCo[i][j] = make_float2(
                        0.0f, ls[i] * ls[i] * (ms_suf[i] - 0.75f * ms[i]) + Is_suf[i]);
                } else {
                    const int mx = (i > j) ? i : j;
                    sCo[i][j] = make_float2(
                        ls[i] * ls[j] * (ms_suf[mx] - 0.5f * ms[mx]), Is_suf[mx]);
                }
            }
        }
    }
    __syncthreads();

    const int nPairs = Btot >> 1;                        // float2 elements
    int t2 = blockIdx.x * blockDim.x + threadIdx.x;      // pair index
    const bool valid = (t2 < nPairs);
    if (!valid) t2 = nPairs - 1;                         // keep shuffle groups uniform
    const int l = threadIdx.x & 3;                       // lane within sample
    const int e0 = 2 * l, e1 = 2 * l + 1;                // owned rows/elements

    // ---- coalesced float2 loads ----
    const float2 q2 = ((const float2*)q_in)[t2];
    const float2 v2 = ((const float2*)v_in)[t2];
    const float v0 = v2.x, v1 = v2.y;

    // ---- segmented scans over 8 elements (2/lane, width-4 shuffles) ----
    float sq = q2.x + q2.y;   // lane totals
    float sv = v0 + v1;
#pragma unroll
    for (int d = 1; d < 4; d <<= 1) {
        const float uq = __shfl_up_sync(FULLMASK, sq, d, 4);
        const float uv = __shfl_up_sync(FULLMASK, sv, d, 4);
        if (l >= d) { sq += uq; sv += uv; }
    }
    const float cs1 = sq, cs0 = sq - q2.y;   // inclusive cumsum of q
    const float cv1 = sv, cv0 = sv - v1;     // inclusive cumsum of v

    const float sn0 = __sinf(cs0), cn0 = __cosf(cs0);
    const float sn1 = __sinf(cs1), cn1 = __cosf(cs1);
    const float vcv0 = v0 * cv0, vcv1 = v1 * cv1;

    // ---- build both owned matrix rows + Coriolis contractions ----
    float m0[NQ], m1[NQ];
    float r10 = 0.0f, r20 = 0.0f, r11 = 0.0f, r21 = 0.0f;
#pragma unroll
    for (int j = 0; j < NQ; j++) {
        const int src = j >> 1;  // compile-time
        const float snj  = __shfl_sync(FULLMASK, (j & 1) ? sn1 : sn0, src, 4);
        const float cnj  = __shfl_sync(FULLMASK, (j & 1) ? cn1 : cn0, src, 4);
        const float vj   = __shfl_sync(FULLMASK, (j & 1) ? v1  : v0,  src, 4);
        const float vcvj = __shfl_sync(FULLMASK, (j & 1) ? vcv1 : vcv0, src, 4);

        const float2 c0 = sCo[e0][j];
        const float cd0 = cn0 * cnj + sn0 * snj;
        const float sd0 = sn0 * cnj - cn0 * snj;
        m0[j] = c0.x * cd0 + c0.y;
        const float T0 = c0.x * sd0;
        r10 += T0 * vj;
        r20 += T0 * vcvj;

        const float2 c1 = sCo[e1][j];
        const float cd1 = cn1 * cnj + sn1 * snj;
        const float sd1 = sn1 * cnj - cn1 * snj;
        m1[j] = c1.x * cd1 + c1.y;
        const float T1 = c1.x * sd1;
        r11 += T1 * vj;
        r21 += T1 * vcvj;
    }

    // ---- suffix sums (inclusive, from high index down) ----
    const float gA = sGc[e0] * sn0;
    const float gB = sGc[e1] * sn1;
    const float rA = v0 * r10;
    float sR = rA + v1 * r11;
    float sG = gA + gB;
#pragma unroll
    for (int d = 1; d < 4; d <<= 1) {
        const float dR = __shfl_down_sync(FULLMASK, sR, d, 4);
        const float dG = __shfl_down_sync(FULLMASK, sG, d, 4);
        if (l + d < 4) { sR += dR; sG += dG; }
    }
    const float suffR0 = sR, suffR1 = sR - rA;
    const float suffG0 = sG, suffG1 = sG - gA;

    // ---- rhs ----
    const float2 u2 = ((const float2*)u_in)[t2];
    float x0 = sTau[e0] * u2.x - (-cv0 * r10 + r20 + suffR0) - suffG0;
    float x1 = sTau[e1] * u2.y - (-cv1 * r11 + r21 + suffR1) - suffG1;

    // ---- lane-parallel Gaussian elimination (SPD, no pivoting) ----
    float dinv0 = 0.0f, dinv1 = 0.0f;
#pragma unroll
    for (int k = 0; k < NQ; k++) {
        const int ok = k >> 1;  // owner lane (compile-time)
        const float pivkk = __shfl_sync(FULLMASK, (k & 1) ? m1[k] : m0[k], ok, 4);
        const float inv = __fdividef(1.0f, pivkk);
        if (l == ok) { if (k & 1) dinv1 = inv; else dinv0 = inv; }
        const bool a0 = (e0 > k), a1 = (e1 > k);
        const float f0 = m0[k] * inv;
        const float f1 = m1[k] * inv;
#pragma unroll
        for (int j = k + 1; j < NQ; j++) {
            const float pj = __shfl_sync(FULLMASK, (k & 1) ? m1[j] : m0[j], ok, 4);
            if (a0) m0[j] -= f0 * pj;
            if (a1) m1[j] -= f1 * pj;
        }
        const float px = __shfl_sync(FULLMASK, (k & 1) ? x1 : x0, ok, 4);
        if (a0) x0 -= f0 * px;
        if (a1) x1 -= f1 * px;
    }

    // ---- back substitution ----
#pragma unroll
    for (int k = NQ - 1; k >= 0; k--) {
        const int ok = k >> 1;
        const float sOwn = (k & 1) ? x1 * dinv1 : x0 * dinv0;
        const float s = __shfl_sync(FULLMASK, sOwn, ok, 4);
        if (l == ok) { if (k & 1) x1 = s; else x0 = s; }
        if (e0 < k) x0 -= m0[k] * s;
        if (e1 < k) x1 -= m1[k] * s;
    }

    if (valid) ((float2*)out)[t2] = make_float2(x0, x1);
}

extern "C" void kernel_launch(void* const* d_in, const int* in_sizes, int n_in,
                              void* d_out, int out_size) {
    const float* q = (const float*)d_in[0];
    const float* v = (const float*)d_in[1];
    const float* u = (const float*)d_in[2];
    const float* p = (const float*)d_in[3];
    float* out = (float*)d_out;
    const int Btot = in_sizes[0];       // B*NQ elements
    const int nThreads = Btot / 2;      // one thread per float2
    const int threads = 256;
    const int blocks = (nThreads + threads - 1) / threads;
    acrobot_dyn_kernel<<<blocks, threads>>>(q, v, u, p, out, Btot);
}

// round 10
// speedup vs baseline: 1.1626x; 1.1626x over previous
#include <cuda_runtime.h>
#include <cuda_bf16.h>

#define NQ 8
#define FULLMASK 0xffffffffu

// One sample per 2 lanes; lane l owns matrix rows e = 4l .. 4l+3.
__global__ void __launch_bounds__(128, 5) acrobot_dyn_kernel(
    const float* __restrict__ q_in, const float* __restrict__ v_in,
    const float* __restrict__ u_in, const float* __restrict__ p,
    float* __restrict__ out, int Btot /* = B*NQ */)
{
    // ---- uniform coefficient tables (once per CTA) ----
    // sCo[i][j] = (A, IsOrD): off-diag A = ls_i*ls_j*(ms_suf_mx - .5*ms_mx), Is_suf[mx];
    //             diag       A = 0,     D[i].
    __shared__ float2 sCo[NQ][NQ + 1];
    __shared__ float sGc[NQ];   // g * ls_k * (ms_suf_k - 0.5*ms_k)
    __shared__ float sTau[NQ];

    if (threadIdx.x == 0) {
        float ms[NQ], ls[NQ], ms_suf[NQ], Is_suf[NQ];
#pragma unroll
        for (int i = 0; i < NQ; i++) {
            ms[i] = p[i];
            ls[i] = p[NQ + i];
            sTau[i] = p[2 * NQ + 1 + i];
        }
        const float g = p[2 * NQ];
        float a = 0.0f, c = 0.0f;
#pragma unroll
        for (int i = NQ - 1; i >= 0; i--) {
            a += ms[i];
            c += ms[i] * ls[i] * ls[i] * (1.0f / 12.0f);
            ms_suf[i] = a;
            Is_suf[i] = c;
        }
#pragma unroll
        for (int i = 0; i < NQ; i++) {
            sGc[i] = g * ls[i] * (ms_suf[i] - 0.5f * ms[i]);
#pragma unroll
            for (int j = 0; j < NQ; j++) {
                if (i == j) {
                    sCo[i][j] = make_float2(
                        0.0f, ls[i] * ls[i] * (ms_suf[i] - 0.75f * ms[i]) + Is_suf[i]);
                } else {
                    const int mx = (i > j) ? i : j;
                    sCo[i][j] = make_float2(
                        ls[i] * ls[j] * (ms_suf[mx] - 0.5f * ms[mx]), Is_suf[mx]);
                }
            }
        }
    }
    __syncthreads();

    const int nQuads = Btot >> 2;                        // float4 elements
    int t4 = blockIdx.x * blockDim.x + threadIdx.x;      // quad index
    const bool valid = (t4 < nQuads);
    if (!valid) t4 = nQuads - 1;                         // keep shuffle pairs uniform
    const int l = threadIdx.x & 1;                       // lane within sample
    const int ebase = l * 4;                             // first owned row

    // ---- coalesced float4 loads ----
    const float4 q4 = ((const float4*)q_in)[t4];
    const float4 v4 = ((const float4*)v_in)[t4];
    const float vv[4] = {v4.x, v4.y, v4.z, v4.w};

    // ---- cumsums: per-thread prefix + one cross-lane shuffle each ----
    float cs[4], cv[4];
    cs[0] = q4.x; cs[1] = cs[0] + q4.y; cs[2] = cs[1] + q4.z; cs[3] = cs[2] + q4.w;
    cv[0] = v4.x; cv[1] = cv[0] + v4.y; cv[2] = cv[1] + v4.z; cv[3] = cv[2] + v4.w;
    {
        const float tq0 = __shfl_sync(FULLMASK, cs[3], 0, 2);  // lane-0 totals
        const float tv0 = __shfl_sync(FULLMASK, cv[3], 0, 2);
        if (l) {
#pragma unroll
            for (int i = 0; i < 4; i++) { cs[i] += tq0; cv[i] += tv0; }
        }
    }

    float sn[4], cn[4], vcv[4];
#pragma unroll
    for (int i = 0; i < 4; i++) {
        sn[i] = __sinf(cs[i]);
        cn[i] = __cosf(cs[i]);
        vcv[i] = vv[i] * cv[i];
    }

    // ---- build 4 owned matrix rows + Coriolis contractions ----
    float m[32];        // m[r*8+j] = M[ebase+r][j]
    float r1[4] = {0.f, 0.f, 0.f, 0.f}, r2[4] = {0.f, 0.f, 0.f, 0.f};
#pragma unroll
    for (int j = 0; j < NQ; j++) {
        const int jl = j >> 2, ji = j & 3;  // compile-time
        const float snj  = __shfl_sync(FULLMASK, sn[ji],  jl, 2);
        const float cnj  = __shfl_sync(FULLMASK, cn[ji],  jl, 2);
        const float vj   = __shfl_sync(FULLMASK, vv[ji],  jl, 2);
        const float vcvj = __shfl_sync(FULLMASK, vcv[ji], jl, 2);
#pragma unroll
        for (int r = 0; r < 4; r++) {
            const float2 c = sCo[ebase + r][j];
            const float cd = cn[r] * cnj + sn[r] * snj;   // cos(cs_e - cs_j)
            const float sd = sn[r] * cnj - cn[r] * snj;   // sin(cs_e - cs_j)
            m[r * 8 + j] = c.x * cd + c.y;                // diag handled by (A=0, D)
            const float T = c.x * sd;
            r1[r] += T * vj;
            r2[r] += T * vcvj;
        }
    }

    // ---- suffix sums across 8 elements (4/lane, one shuffle each) ----
    float suffR[4], suffG[4];
    {
        float pr = 0.f, pg = 0.f;
#pragma unroll
        for (int r = 3; r >= 0; r--) {
            pr += vv[r] * r1[r];
            pg += sGc[ebase + r] * sn[r];
            suffR[r] = pr;
            suffG[r] = pg;
        }
        const float tR1 = __shfl_sync(FULLMASK, suffR[0], 1, 2);  // lane-1 totals
        const float tG1 = __shfl_sync(FULLMASK, suffG[0], 1, 2);
        if (l == 0) {
#pragma unroll
            for (int r = 0; r < 4; r++) { suffR[r] += tR1; suffG[r] += tG1; }
        }
    }

    // ---- rhs ----
    const float4 u4 = ((const float4*)u_in)[t4];
    const float uu[4] = {u4.x, u4.y, u4.z, u4.w};
    float x[4];
#pragma unroll
    for (int r = 0; r < 4; r++) {
        const float Cv = -cv[r] * r1[r] + r2[r] + suffR[r];
        x[r] = sTau[ebase + r] * uu[r] - Cv - suffG[r];
    }

    // ---- lane-parallel Gaussian elimination (SPD, no pivoting) ----
    float dinv[4] = {0.f, 0.f, 0.f, 0.f};
#pragma unroll
    for (int k = 0; k < NQ; k++) {
        const int ok = k >> 2, ki = k & 3;  // owner lane / local row (compile-time)
        const float pivkk = __shfl_sync(FULLMASK, m[ki * 8 + k], ok, 2);
        const float inv = __fdividef(1.0f, pivkk);
        if (l == ok) dinv[ki] = inv;
        float f[4];
#pragma unroll
        for (int r = 0; r < 4; r++) f[r] = m[r * 8 + k] * inv;
#pragma unroll
        for (int j = k + 1; j < NQ; j++) {
            const float pj = __shfl_sync(FULLMASK, m[ki * 8 + j], ok, 2);
#pragma unroll
            for (int r = 0; r < 4; r++)
                if (ebase + r > k) m[r * 8 + j] -= f[r] * pj;
        }
        const float px = __shfl_sync(FULLMASK, x[ki], ok, 2);
#pragma unroll
        for (int r = 0; r < 4; r++)
            if (ebase + r > k) x[r] -= f[r] * px;
    }

    // ---- back substitution ----
#pragma unroll
    for (int k = NQ - 1; k >= 0; k--) {
        const int ok = k >> 2, ki = k & 3;
        const float sOwn = x[ki] * dinv[ki];
        const float s = __shfl_sync(FULLMASK, sOwn, ok, 2);
        if (l == ok) x[ki] = s;
#pragma unroll
        for (int r = 0; r < 4; r++)
            if (ebase + r < k) x[r] -= m[r * 8 + k] * s;
    }

    if (valid) ((float4*)out)[t4] = make_float4(x[0], x[1], x[2], x[3]);
}

extern "C" void kernel_launch(void* const* d_in, const int* in_sizes, int n_in,
                              void* d_out, int out_size) {
    const float* q = (const float*)d_in[0];
    const float* v = (const float*)d_in[1];
    const float* u = (const float*)d_in[2];
    const float* p = (const float*)d_in[3];
    float* out = (float*)d_out;
    const int Btot = in_sizes[0];       // B*NQ elements
    const int nThreads = Btot / 4;      // one thread per float4
    const int threads = 128;
    const int blocks = (nThreads + threads - 1) / threads;
    acrobot_dyn_kernel<<<blocks, threads>>>(q, v, u, p, out, Btot);
}